// round 13
// baseline (speedup 1.0000x reference)
#include <cuda_runtime.h>
#include <cuda_fp16.h>
#include <cstdint>
#include <cstddef>

// ---------------------------------------------------------------------------
// 50-layer LSTM, persistent wavefront, fp16 m16n8k16 mma.sync.
//   B=64, T=256, D=H=256, L=50, O=2
//   R13: 100 CTAs (1/SM, balanced), 512 threads = TWO independent 256-thread
//        groups (named barriers, separate SMEM arenas, separate flags).
//        Each group = R11 quarter-layer worker (64 units, 8 warps, 64x32
//        warp tile). Cross-group overlap hides phase latency on EVERY SM.
//        Staging via cp.async.
// ---------------------------------------------------------------------------

#define LAYERS 50
#define TSTEPS 256
#define GPL    4                           // quarters per layer
#define NCTA   (LAYERS*2)                  // 100 CTAs, 2 quarters per CTA
#define HSLOT  16384                       // 64*256 halves per time slot
#define HLAYER ((size_t)(TSTEPS+1)*HSLOT)

#define SA_STRIDE 520                      // halves per SMEM A row
#define CB_STRIDE 72                       // floats per cbuf row (64 units)
#define W_WARP_HALVES 16384                // per (l,gg,wn): 32kt*512 halves
#define GRP_BYTES (64*SA_STRIDE*2 + 64*CB_STRIDE*4 + 256*4)   // 86016
#define SMEM_BYTES (2*GRP_BYTES)                               // 172032

__device__ __half   g_h16[(size_t)LAYERS*HLAYER];                 // ~421 MB
__device__ __half   g_w16[(size_t)LAYERS*GPL*8*W_WARP_HALVES];    // ~52 MB
__device__ float    g_bias[LAYERS*1024];
__device__ unsigned g_prog[256];

// ------------------------------- helpers -----------------------------------

__device__ __forceinline__ unsigned long long ld_acq64(const unsigned* p) {
    unsigned long long v;
    asm volatile("ld.acquire.gpu.u64 %0, [%1];" : "=l"(v) : "l"(p) : "memory");
    return v;
}
__device__ __forceinline__ void st_rel(unsigned* p, unsigned v) {
    asm volatile("st.release.gpu.u32 [%0], %1;" :: "l"(p), "r"(v) : "memory");
}
__device__ __forceinline__ void mma16(float* acc, const uint32_t a[4],
                                      uint32_t b0, uint32_t b1) {
    asm("mma.sync.aligned.m16n8k16.row.col.f32.f16.f16.f32 "
        "{%0,%1,%2,%3},{%4,%5,%6,%7},{%8,%9},{%0,%1,%2,%3};"
        : "+f"(acc[0]), "+f"(acc[1]), "+f"(acc[2]), "+f"(acc[3])
        : "r"(a[0]), "r"(a[1]), "r"(a[2]), "r"(a[3]), "r"(b0), "r"(b1));
}
__device__ __forceinline__ void ldsm4(uint32_t r[4], uint32_t saddr) {
    asm volatile("ldmatrix.sync.aligned.m8n8.x4.shared.b16 {%0,%1,%2,%3}, [%4];"
        : "=r"(r[0]), "=r"(r[1]), "=r"(r[2]), "=r"(r[3]) : "r"(saddr));
}
__device__ __forceinline__ void cpa16(uint32_t dst, const void* src) {
    asm volatile("cp.async.cg.shared.global [%0], [%1], 16;"
                 :: "r"(dst), "l"(src));
}
__device__ __forceinline__ void cpa_wait_all() {
    asm volatile("cp.async.wait_all;" ::: "memory");
}
__device__ __forceinline__ float tanhfast(float x) {
    float y;
    asm("tanh.approx.f32 %0, %1;" : "=f"(y) : "f"(x));
    return y;
}
__device__ __forceinline__ float sigm(float x) {          // 1 MUFU
    return fmaf(tanhfast(0.5f * x), 0.5f, 0.5f);
}
// group-scoped named barrier (256 threads), ids 1 and 2
#define GBAR(G) asm volatile("bar.sync %0, 256;" :: "r"(1 + (G)) : "memory")

// ------------------------------ prep kernels --------------------------------

// Pack weights into uint4-loadable fp16 B fragments, gate-blocked columns.
// half index: [l][gg(4)][wn(8)][kt(32)][j(2)][lane(32)][h(8)]
// Quarter gg owns units [64gg, 64gg+64); warp wn owns 8 of them.
__global__ void prep_wfrag16(const float* __restrict__ Wih,
                             const float* __restrict__ Whh) {
    size_t idx = (size_t)blockIdx.x * 256 + threadIdx.x;
    int h    = (int)(idx & 7);
    int lane = (int)((idx >> 3)  & 31);
    int j    = (int)((idx >> 8)  & 1);
    int kt   = (int)((idx >> 9)  & 31);
    int wn   = (int)((idx >> 14) & 7);
    int gg   = (int)((idx >> 17) & 3);
    int l    = (int)(idx >> 19);
    if (l >= LAYERS) return;
    int jj = h >> 1, hb = h & 1;
    int nt  = j * 2 + (jj >> 1);             // gate 0..3 (i,f,g,o)
    int col = lane >> 2;                     // unit offset 0..7
    int k   = kt * 16 + (lane & 3) * 2 + hb + (jj & 1) * 8;
    int r = nt * 256 + gg * 64 + wn * 8 + col;
    float v = (k < 256) ? Wih[((size_t)l * 1024 + r) * 256 + k]
                        : Whh[((size_t)l * 1024 + r) * 256 + (k - 256)];
    g_w16[idx] = __float2half(v);
}

// sbias[l][gg(4)][wn*32 + nt*8 + cc]
__global__ void prep_bias_init(const float* __restrict__ bih,
                               const float* __restrict__ bhh) {
    int idx = blockIdx.x * 256 + threadIdx.x;
    if (idx < LAYERS * 1024) {
        int l  = idx >> 10;
        int nl = idx & 1023;
        int gg = nl >> 8;
        int nn = nl & 255;
        int wn = nn >> 5;
        int nt = (nn >> 3) & 3;
        int cc = nn & 7;
        int r = nt * 256 + gg * 64 + wn * 8 + cc;
        g_bias[idx] = bih[l * 1024 + r] + bhh[l * 1024 + r];
    }
    if (idx < 256) g_prog[idx] = 0;
}

__global__ void zero_h0() {
    uint4* p = (uint4*)(g_h16 + (size_t)blockIdx.x * HLAYER);  // slot 0
    for (int i = threadIdx.x; i < 2048; i += 256)
        p[i] = make_uint4(0u, 0u, 0u, 0u);
}

// --------------------------- persistent LSTM --------------------------------

#define MMA_BLOCK(B0, B1)                                                     \
    _Pragma("unroll")                                                         \
    for (int mt = 0; mt < 4; ++mt) {                                          \
        mma16(acc[mt][0], av[mt], (B0).x, (B0).y);                            \
        mma16(acc[mt][1], av[mt], (B0).z, (B0).w);                            \
        mma16(acc[mt][2], av[mt], (B1).x, (B1).y);                            \
        mma16(acc[mt][3], av[mt], (B1).z, (B1).w);                            \
    }

__global__ void __launch_bounds__(512, 1)
lstm_persistent(const float* __restrict__ x) {
    extern __shared__ char smem[];
    const int tid  = threadIdx.x;
    const int g    = tid >> 8;      // group 0/1 — independent worker
    const int gtid = tid & 255;
    const int lane = tid & 31;
    const int wn   = (gtid >> 5);   // 0..7 : 8-unit group
    const int q    = lane & 3;

    const int l  = blockIdx.x >> 1;
    const int gg = (blockIdx.x & 1) * 2 + g;   // quarter 0..3

    char*   base  = smem + g * GRP_BYTES;
    __half* sA    = (__half*)base;                                 // 64*520
    float*  cbuf  = (float*)(base + 64 * SA_STRIDE * 2);           // 64*72
    float*  sbias = (float*)(base + 64 * SA_STRIDE * 2 + 64 * CB_STRIDE * 4);

    sbias[gtid] = g_bias[(l * GPL + gg) * 256 + gtid];
    for (int i = gtid; i < 64 * CB_STRIDE; i += 256) cbuf[i] = 0.f;
    // zero own h quarter in sA (h_{-1}=0); peer quarters staged from global
    for (int i = gtid; i < 512; i += 256) {
        int row = i >> 3, c8 = i & 7;
        *(uint4*)(sA + row * SA_STRIDE + 256 + gg * 64 + c8 * 8) =
            make_uint4(0u, 0u, 0u, 0u);
    }
    __syncthreads();   // once, before the groups diverge

    const uint4* wv = (const uint4*)(g_w16 +
        (size_t)((l * GPL + gg) * 8 + wn) * W_WARP_HALVES);
    __half* hlayer = g_h16 + (size_t)l * HLAYER;
    const __half* hprev = (l > 0) ? (g_h16 + (size_t)(l - 1) * HLAYER) : nullptr;

    uint32_t sA_base = (uint32_t)__cvta_generic_to_shared(sA);
    const int rowA = lane & 15;
    const int kofA = (lane >> 4) * 8;

    float acc[4][4][4];        // [mt][gate][frag] : 64 regs

    for (int t = 0; t < TSTEPS; ++t) {
        // ---- wait: all layer quarters >= t, all prev-layer quarters >= t+1
        if (gtid == 0) {
            if (t > 0) {
                const unsigned need = (unsigned)t;
                for (;;) {
                    unsigned long long a = ld_acq64(&g_prog[l * 4]);
                    unsigned long long b = ld_acq64(&g_prog[l * 4 + 2]);
                    if ((unsigned)a >= need && (unsigned)(a >> 32) >= need &&
                        (unsigned)b >= need && (unsigned)(b >> 32) >= need)
                        break;
                    __nanosleep(32);
                }
            }
            if (l > 0) {
                const unsigned need = (unsigned)(t + 1);
                for (;;) {
                    unsigned long long a = ld_acq64(&g_prog[(l - 1) * 4]);
                    unsigned long long b = ld_acq64(&g_prog[(l - 1) * 4 + 2]);
                    if ((unsigned)a >= need && (unsigned)(a >> 32) >= need &&
                        (unsigned)b >= need && (unsigned)(b >> 32) >= need)
                        break;
                    __nanosleep(32);
                }
            }
        }
        GBAR(g);

        // ---- stage x_t -> sA[0,256), 3 peer h quarters (cp.async) ----
        if (l == 0) {
            #pragma unroll
            for (int i = gtid; i < 4096; i += 256) {      // 64 rows * 64 float4
                int row = i >> 6, c4 = i & 63;
                float4 v = __ldg((const float4*)(x +
                              ((size_t)row * TSTEPS + t) * 256) + c4);
                __half2* dst = (__half2*)(sA + row * SA_STRIDE + c4 * 4);
                dst[0] = __floats2half2_rn(v.x, v.y);
                dst[1] = __floats2half2_rn(v.z, v.w);
            }
        } else {
            const __half* src = hprev + (size_t)(t + 1) * HSLOT;
            #pragma unroll
            for (int i = gtid; i < 2048; i += 256) {      // 64 rows * 32 x 16B
                int row = i >> 5, c8 = i & 31;
                cpa16(sA_base + (uint32_t)((row * SA_STRIDE + c8 * 8) * 2),
                      src + (size_t)row * 256 + c8 * 8);
            }
        }
        {
            const __half* hsl = hlayer + (size_t)t * HSLOT;
            #pragma unroll
            for (int i = gtid; i < 1536; i += 256) {      // 3 * 64 rows * 8 x 16B
                int pi  = i >> 9;                          // 0..2
                int pg  = pi + (pi >= gg);                 // skip own quarter
                int rem = i & 511;
                int row = rem >> 3, c8 = rem & 7;
                cpa16(sA_base + (uint32_t)((row * SA_STRIDE + 256 + pg * 64 + c8 * 8) * 2),
                      hsl + (size_t)row * 256 + pg * 64 + c8 * 8);
            }
        }

        // ---- init accumulators with bias (overlaps cp.async) ----
        #pragma unroll
        for (int nt = 0; nt < 4; ++nt) {
            float b0 = sbias[wn * 32 + nt * 8 + q * 2];
            float b1 = sbias[wn * 32 + nt * 8 + q * 2 + 1];
            #pragma unroll
            for (int mt = 0; mt < 4; ++mt) {
                acc[mt][nt][0] = b0; acc[mt][nt][1] = b1;
                acc[mt][nt][2] = b0; acc[mt][nt][3] = b1;
            }
        }
        cpa_wait_all();
        GBAR(g);

        // ---- GEMM: gates += [x_t | h_{t-1}] @ Wc^T, depth-2 B prefetch ----
        {
            uint4 b0a = __ldg(wv + lane);
            uint4 b0b = __ldg(wv + 32 + lane);
            uint4 b1a = __ldg(wv + 64 + lane);
            uint4 b1b = __ldg(wv + 96 + lane);
            #pragma unroll 4
            for (int kt = 0; kt < 32; ++kt) {
                uint32_t av[4][4];
                #pragma unroll
                for (int mt = 0; mt < 4; ++mt) {
                    uint32_t addr = sA_base + (uint32_t)(
                        ((mt * 16 + rowA) * SA_STRIDE + kt * 16 + kofA) * 2);
                    ldsm4(av[mt], addr);
                }
                uint4 na, nb;
                if (kt < 30) {
                    na = __ldg(wv + (kt + 2) * 64 + lane);
                    nb = __ldg(wv + (kt + 2) * 64 + 32 + lane);
                }
                if (kt & 1) {
                    MMA_BLOCK(b1a, b1b)
                    if (kt < 30) { b1a = na; b1b = nb; }
                } else {
                    MMA_BLOCK(b0a, b0b)
                    if (kt < 30) { b0a = na; b0b = nb; }
                }
            }
        }
        GBAR(g);   // all LDSM done before sA h-region is rewritten

        // ---- elementwise LSTM update (tanh.approx, c in SMEM) ----
        // element (mt,j): row = mt*16 + (lane>>2) + (j>>1)*8,
        // local unit u0 = wn*8 + 2q + (j&1); gates acc[mt][0..3][j] = i,f,g,o
        __half* houtg = hlayer + (size_t)(t + 1) * HSLOT + gg * 64;
        __half* houts = sA + 256 + gg * 64;
        const int rbase = lane >> 2;
        const int u0 = wn * 8 + 2 * q;
        #pragma unroll
        for (int mt = 0; mt < 4; ++mt) {
            int row0 = mt * 16 + rbase;
            float2 c01 = *(float2*)&cbuf[row0 * CB_STRIDE + u0];
            float2 c23 = *(float2*)&cbuf[(row0 + 8) * CB_STRIDE + u0];
            float cv[4] = {c01.x, c01.y, c23.x, c23.y};
            float hv[4];
            #pragma unroll
            for (int j = 0; j < 4; ++j) {
                float i_ = sigm(acc[mt][0][j]);
                float f_ = sigm(acc[mt][1][j]);
                float g_ = tanhfast(acc[mt][2][j]);
                float o_ = sigm(acc[mt][3][j]);
                float cn = fmaf(f_, cv[j], i_ * g_);
                cv[j] = cn;
                hv[j] = o_ * tanhfast(cn);
            }
            *(float2*)&cbuf[row0 * CB_STRIDE + u0]       = make_float2(cv[0], cv[1]);
            *(float2*)&cbuf[(row0 + 8) * CB_STRIDE + u0] = make_float2(cv[2], cv[3]);
            __half2 h01 = __floats2half2_rn(hv[0], hv[1]);
            __half2 h23 = __floats2half2_rn(hv[2], hv[3]);
            *(__half2*)(houtg + (size_t)row0 * 256 + u0)       = h01;
            *(__half2*)(houtg + (size_t)(row0 + 8) * 256 + u0) = h23;
            *(__half2*)(houts + row0 * SA_STRIDE + u0)         = h01;
            *(__half2*)(houts + (row0 + 8) * SA_STRIDE + u0)   = h23;
        }

        GBAR(g);
        if (gtid == 0) st_rel(&g_prog[l * GPL + gg], (unsigned)(t + 1));
    }
}

// ------------------------------ output head ---------------------------------

__global__ void out_proj(const float* __restrict__ Wout,
                         const float* __restrict__ bout,
                         float* __restrict__ out) {
    int p = blockIdx.x * 8 + (threadIdx.x >> 5);   // (t*64+b), 16384 total
    int lane = threadIdx.x & 31;
    int t = p >> 6, b = p & 63;
    const __half* h = g_h16 + (size_t)(LAYERS - 1) * HLAYER +
                      (size_t)(t + 1) * HSLOT + (size_t)b * 256 + lane * 8;
    uint4 hv = *(const uint4*)h;
    const __half2* hh = (const __half2*)&hv;
    const float* w0 = Wout + lane * 8;
    const float* w1 = Wout + 256 + lane * 8;
    float s0 = 0.f, s1 = 0.f;
    #pragma unroll
    for (int j = 0; j < 4; ++j) {
        float2 f = __half22float2(hh[j]);
        s0 += f.x * w0[2 * j] + f.y * w0[2 * j + 1];
        s1 += f.x * w1[2 * j] + f.y * w1[2 * j + 1];
    }
    #pragma unroll
    for (int off = 16; off > 0; off >>= 1) {
        s0 += __shfl_xor_sync(0xffffffffu, s0, off);
        s1 += __shfl_xor_sync(0xffffffffu, s1, off);
    }
    if (lane == 0) {
        float e0 = __expf(-(s0 + bout[0]));
        float e1 = __expf(-(s1 + bout[1]));
        out[(size_t)b * (TSTEPS * 2) + t * 2 + 0] = __fdividef(1.f, 1.f + e0);
        out[(size_t)b * (TSTEPS * 2) + t * 2 + 1] = __fdividef(1.f, 1.f + e1);
    }
}

// ------------------------------- launcher -----------------------------------

extern "C" void kernel_launch(void* const* d_in, const int* in_sizes, int n_in,
                              void* d_out, int out_size) {
    const float* x    = (const float*)d_in[0];
    const float* Wih  = (const float*)d_in[1];
    const float* Whh  = (const float*)d_in[2];
    const float* bih  = (const float*)d_in[3];
    const float* bhh  = (const float*)d_in[4];
    const float* Wout = (const float*)d_in[5];
    const float* bout = (const float*)d_in[6];
    float* out = (float*)d_out;

    cudaFuncSetAttribute(lstm_persistent,
                         cudaFuncAttributeMaxDynamicSharedMemorySize, SMEM_BYTES);

    prep_wfrag16<<<102400, 256>>>(Wih, Whh);    // 26.2M packed fp16 fragments
    prep_bias_init<<<200, 256>>>(bih, bhh);     // bias permute + progress reset
    zero_h0<<<LAYERS, 256>>>();                 // h_{-1} = 0 slots (fp16)
    lstm_persistent<<<NCTA, 512, SMEM_BYTES>>>(x);
    out_proj<<<2048, 256>>>(Wout, bout, out);   // final sigmoid head
}

// round 14
// speedup vs baseline: 1.1987x; 1.1987x over previous
#include <cuda_runtime.h>
#include <cuda_fp16.h>
#include <cstdint>
#include <cstddef>

// ---------------------------------------------------------------------------
// 50-layer LSTM, persistent wavefront, fp16 m16n8k16 mma.sync.
//   B=64, T=256, D=H=256, L=50, O=2
//   R14: R10 base (100 CTAs 1/SM, 512 thr, warp tile 64x32) +
//        per-warp cp.async depth-4 SMEM pipeline for B weights:
//        LDGSTS off the HMMA dependency chain, zero barriers in GEMM
//        (each lane copies exactly the bytes it later reads).
// ---------------------------------------------------------------------------

#define LAYERS 50
#define TSTEPS 256
#define GPL    2
#define NCTA   (LAYERS*GPL)                // 100 persistent CTAs, 1 per SM
#define HSLOT  16384                       // 64*256 halves per time slot
#define HLAYER ((size_t)(TSTEPS+1)*HSLOT)

#define SA_STRIDE 520                      // halves per SMEM A row
#define CB_STRIDE 136                      // floats per cbuf row
#define W_WARP_HALVES 16384                // per (l,gg,wn): 32kt*512 halves
#define SB_STAGE 16384                     // bytes per B stage (16 warps * 1KB)
#define NSTAGE 4
#define OFF_CB   (64*SA_STRIDE*2)                       // 66560
#define OFF_BIAS (OFF_CB + 64*CB_STRIDE*4)              // 101376
#define OFF_SB   (OFF_BIAS + 512*4)                     // 103424
#define SMEM_BYTES (OFF_SB + NSTAGE*SB_STAGE)           // 168960

__device__ __half   g_h16[(size_t)LAYERS*HLAYER];                 // ~421 MB
__device__ __half   g_w16[(size_t)LAYERS*2*16*W_WARP_HALVES];     // ~52 MB
__device__ float    g_bias[LAYERS*1024];
__device__ unsigned g_prog[128];

// ------------------------------- helpers -----------------------------------

__device__ __forceinline__ unsigned ld_acq(const unsigned* p) {
    unsigned v;
    asm volatile("ld.acquire.gpu.u32 %0, [%1];" : "=r"(v) : "l"(p) : "memory");
    return v;
}
__device__ __forceinline__ unsigned long long ld_acq64(const unsigned* p) {
    unsigned long long v;
    asm volatile("ld.acquire.gpu.u64 %0, [%1];" : "=l"(v) : "l"(p) : "memory");
    return v;
}
__device__ __forceinline__ void st_rel(unsigned* p, unsigned v) {
    asm volatile("st.release.gpu.u32 [%0], %1;" :: "l"(p), "r"(v) : "memory");
}
__device__ __forceinline__ void mma16(float* acc, const uint32_t a[4],
                                      uint32_t b0, uint32_t b1) {
    asm("mma.sync.aligned.m16n8k16.row.col.f32.f16.f16.f32 "
        "{%0,%1,%2,%3},{%4,%5,%6,%7},{%8,%9},{%0,%1,%2,%3};"
        : "+f"(acc[0]), "+f"(acc[1]), "+f"(acc[2]), "+f"(acc[3])
        : "r"(a[0]), "r"(a[1]), "r"(a[2]), "r"(a[3]), "r"(b0), "r"(b1));
}
__device__ __forceinline__ void ldsm4(uint32_t r[4], uint32_t saddr) {
    asm volatile("ldmatrix.sync.aligned.m8n8.x4.shared.b16 {%0,%1,%2,%3}, [%4];"
        : "=r"(r[0]), "=r"(r[1]), "=r"(r[2]), "=r"(r[3]) : "r"(saddr));
}
__device__ __forceinline__ void cpa16(uint32_t dst, const void* src) {
    asm volatile("cp.async.cg.shared.global [%0], [%1], 16;"
                 :: "r"(dst), "l"(src));
}
__device__ __forceinline__ void cpa_commit() {
    asm volatile("cp.async.commit_group;" ::: "memory");
}
__device__ __forceinline__ uint4 lds128(uint32_t addr) {
    uint4 v;
    asm volatile("ld.shared.v4.u32 {%0,%1,%2,%3}, [%4];"
        : "=r"(v.x), "=r"(v.y), "=r"(v.z), "=r"(v.w) : "r"(addr));
    return v;
}
__device__ __forceinline__ float tanhfast(float x) {
    float y;
    asm("tanh.approx.f32 %0, %1;" : "=f"(y) : "f"(x));
    return y;
}
__device__ __forceinline__ float sigm(float x) {          // 1 MUFU
    return fmaf(tanhfast(0.5f * x), 0.5f, 0.5f);
}

// ------------------------------ prep kernels --------------------------------

// Pack weights into uint4-loadable fp16 B fragments, gate-blocked columns.
// half index: [l][gg(2)][wn(16)][kt(32)][j(2)][lane(32)][h(8)]
// Warp wn owns units [8wn, 8wn+8); its 32 cols = gate(nt) x 8 units.
__global__ void prep_wfrag16(const float* __restrict__ Wih,
                             const float* __restrict__ Whh) {
    size_t idx = (size_t)blockIdx.x * 256 + threadIdx.x;
    int h    = (int)(idx & 7);
    int lane = (int)((idx >> 3)  & 31);
    int j    = (int)((idx >> 8)  & 1);
    int kt   = (int)((idx >> 9)  & 31);
    int wn   = (int)((idx >> 14) & 15);
    int gg   = (int)((idx >> 18) & 1);
    int l    = (int)(idx >> 19);
    if (l >= LAYERS) return;
    int jj = h >> 1, hb = h & 1;
    int nt  = j * 2 + (jj >> 1);             // gate 0..3 (i,f,g,o)
    int col = lane >> 2;                     // unit offset 0..7
    int k   = kt * 16 + (lane & 3) * 2 + hb + (jj & 1) * 8;
    int r = nt * 256 + gg * 128 + wn * 8 + col;
    float v = (k < 256) ? Wih[((size_t)l * 1024 + r) * 256 + k]
                        : Whh[((size_t)l * 1024 + r) * 256 + (k - 256)];
    g_w16[idx] = __float2half(v);
}

// sbias[l][gg][wn*32 + nt*8 + cc]
__global__ void prep_bias_init(const float* __restrict__ bih,
                               const float* __restrict__ bhh) {
    int idx = blockIdx.x * 256 + threadIdx.x;
    if (idx < LAYERS * 1024) {
        int l  = idx >> 10;
        int nl = idx & 1023;
        int gg = nl >> 9;
        int nn = nl & 511;
        int wn = nn >> 5;
        int nt = (nn >> 3) & 3;
        int cc = nn & 7;
        int r = nt * 256 + gg * 128 + wn * 8 + cc;
        g_bias[idx] = bih[l * 1024 + r] + bhh[l * 1024 + r];
    }
    if (idx < 128) g_prog[idx] = 0;
}

__global__ void zero_h0() {
    uint4* p = (uint4*)(g_h16 + (size_t)blockIdx.x * HLAYER);  // slot 0
    for (int i = threadIdx.x; i < 2048; i += 256)
        p[i] = make_uint4(0u, 0u, 0u, 0u);
}

// --------------------------- persistent LSTM --------------------------------

#define MMA_BLOCK(B0, B1)                                                     \
    _Pragma("unroll")                                                         \
    for (int mt = 0; mt < 4; ++mt) {                                          \
        mma16(acc[mt][0], av[mt], (B0).x, (B0).y);                            \
        mma16(acc[mt][1], av[mt], (B0).z, (B0).w);                            \
        mma16(acc[mt][2], av[mt], (B1).x, (B1).y);                            \
        mma16(acc[mt][3], av[mt], (B1).z, (B1).w);                            \
    }

__global__ void __launch_bounds__(512, 1)
lstm_persistent(const float* __restrict__ x) {
    extern __shared__ char smem[];
    __half* sA    = (__half*)smem;                                 // 64*520
    float*  cbuf  = (float*)(smem + OFF_CB);                       // 64*136
    float*  sbias = (float*)(smem + OFF_BIAS);

    const int l    = blockIdx.x >> 1;
    const int gg   = blockIdx.x & 1;
    const int tid  = threadIdx.x;
    const int lane = tid & 31;
    const int wn   = tid >> 5;      // 0..15 : 8-unit group
    const int q    = lane & 3;

    if (tid < 512) sbias[tid] = g_bias[(l * GPL + gg) * 512 + tid];
    for (int i = tid; i < 64 * CB_STRIDE; i += 512) cbuf[i] = 0.f;
    // zero own h half in sA (h_{-1} = 0); peer half comes from global slot 0
    for (int i = tid; i < 1024; i += 512) {
        int row = i >> 4, c8 = i & 15;
        *(uint4*)(sA + row * SA_STRIDE + 256 + gg * 128 + c8 * 8) =
            make_uint4(0u, 0u, 0u, 0u);
    }
    __syncthreads();

    const uint4* wv = (const uint4*)(g_w16 +
        (size_t)((l * GPL + gg) * 16 + wn) * W_WARP_HALVES);
    __half* hlayer = g_h16 + (size_t)l * HLAYER;
    const __half* hprev = (l > 0) ? (g_h16 + (size_t)(l - 1) * HLAYER) : nullptr;

    uint32_t smem_u32 = (uint32_t)__cvta_generic_to_shared(smem);
    uint32_t sA_base  = smem_u32;
    // my lane's B slot within a stage (each lane copies what it reads)
    uint32_t sBw = smem_u32 + OFF_SB + wn * 1024 + lane * 16;

    const int rowA = lane & 15;
    const int kofA = (lane >> 4) * 8;
    const int peer = gg ^ 1;

    float acc[4][4][4];        // [mt][gate][frag] : 64 regs

    for (int t = 0; t < TSTEPS; ++t) {
        // ---- wait: peer >= t (peer h half), prev layer >= t+1 (x ready) ----
        if (tid == 0) {
            if (t > 0) {
                while (ld_acq(&g_prog[l * GPL + peer]) < (unsigned)t)
                    __nanosleep(32);
            }
            if (l > 0) {
                const unsigned need = (unsigned)(t + 1);
                for (;;) {
                    unsigned long long v = ld_acq64(&g_prog[(l - 1) * GPL]);
                    if ((unsigned)v >= need && (unsigned)(v >> 32) >= need) break;
                    __nanosleep(32);
                }
            }
        }
        __syncthreads();

        // ---- stage x_t -> sA[0,256), peer h half -> sA[256+peer*128,+128) --
        if (l == 0) {
            #pragma unroll
            for (int i = tid; i < 4096; i += 512) {       // 64 rows * 64 float4
                int row = i >> 6, c4 = i & 63;
                float4 v = __ldg((const float4*)(x +
                              ((size_t)row * TSTEPS + t) * 256) + c4);
                __half2* dst = (__half2*)(sA + row * SA_STRIDE + c4 * 4);
                dst[0] = __floats2half2_rn(v.x, v.y);
                dst[1] = __floats2half2_rn(v.z, v.w);
            }
        } else {
            const uint4* src = (const uint4*)(hprev + (size_t)(t + 1) * HSLOT);
            #pragma unroll
            for (int i = tid; i < 2048; i += 512) {       // 64 rows * 32 uint4
                int row = i >> 5, c8 = i & 31;
                *(uint4*)(sA + row * SA_STRIDE + c8 * 8) = __ldg(src + i);
            }
        }
        {
            const __half* srcp = hlayer + (size_t)t * HSLOT + peer * 128;
            #pragma unroll
            for (int i = tid; i < 1024; i += 512) {       // 64 rows * 16 uint4
                int row = i >> 4, c8 = i & 15;
                *(uint4*)(sA + row * SA_STRIDE + 256 + peer * 128 + c8 * 8) =
                    __ldg((const uint4*)(srcp + (size_t)row * 256) + c8);
            }
        }

        // ---- init accumulators with bias ----
        #pragma unroll
        for (int nt = 0; nt < 4; ++nt) {
            float b0 = sbias[wn * 32 + nt * 8 + q * 2];
            float b1 = sbias[wn * 32 + nt * 8 + q * 2 + 1];
            #pragma unroll
            for (int mt = 0; mt < 4; ++mt) {
                acc[mt][nt][0] = b0; acc[mt][nt][1] = b1;
                acc[mt][nt][2] = b0; acc[mt][nt][3] = b1;
            }
        }
        __syncthreads();

        // ---- GEMM: gates += [x_t | h_{t-1}] @ Wc^T ----
        // B streamed via per-warp cp.async depth-4 pipeline; no barriers:
        // each lane cp.asyncs exactly the 2x16B it will lds128 later.
        {
            #pragma unroll
            for (int s = 0; s < NSTAGE - 1; ++s) {        // prologue kt=0..2
                cpa16(sBw + s * SB_STAGE,       wv + s * 64 + lane);
                cpa16(sBw + s * SB_STAGE + 512, wv + s * 64 + 32 + lane);
                cpa_commit();
            }
            #pragma unroll 4
            for (int kt = 0; kt < 32; ++kt) {
                const int s = kt & (NSTAGE - 1);
                asm volatile("cp.async.wait_group %0;" :: "n"(NSTAGE - 2) : "memory");
                uint4 bb0 = lds128(sBw + s * SB_STAGE);
                uint4 bb1 = lds128(sBw + s * SB_STAGE + 512);
                uint32_t av[4][4];
                #pragma unroll
                for (int mt = 0; mt < 4; ++mt) {
                    uint32_t addr = sA_base + (uint32_t)(
                        ((mt * 16 + rowA) * SA_STRIDE + kt * 16 + kofA) * 2);
                    ldsm4(av[mt], addr);
                }
                if (kt < 32 - (NSTAGE - 1)) {
                    const int s2 = (kt + NSTAGE - 1) & (NSTAGE - 1);
                    cpa16(sBw + s2 * SB_STAGE,       wv + (kt + NSTAGE - 1) * 64 + lane);
                    cpa16(sBw + s2 * SB_STAGE + 512, wv + (kt + NSTAGE - 1) * 64 + 32 + lane);
                }
                cpa_commit();
                MMA_BLOCK(bb0, bb1)
            }
        }
        __syncthreads();   // all LDSM done before sA h-region is rewritten

        // ---- elementwise LSTM update (tanh.approx, c in SMEM) ----
        // element (mt,j): row = mt*16 + (lane>>2) + (j>>1)*8,
        // unit u0 = wn*8 + 2q + (j&1); gates acc[mt][0..3][j] = i,f,g,o
        __half* houtg = hlayer + (size_t)(t + 1) * HSLOT + gg * 128;
        __half* houts = sA + 256 + gg * 128;
        const int rbase = lane >> 2;
        const int u0 = wn * 8 + 2 * q;
        #pragma unroll
        for (int mt = 0; mt < 4; ++mt) {
            int row0 = mt * 16 + rbase;
            float2 c01 = *(float2*)&cbuf[row0 * CB_STRIDE + u0];
            float2 c23 = *(float2*)&cbuf[(row0 + 8) * CB_STRIDE + u0];
            float cv[4] = {c01.x, c01.y, c23.x, c23.y};
            float hv[4];
            #pragma unroll
            for (int j = 0; j < 4; ++j) {
                float i_ = sigm(acc[mt][0][j]);
                float f_ = sigm(acc[mt][1][j]);
                float g_ = tanhfast(acc[mt][2][j]);
                float o_ = sigm(acc[mt][3][j]);
                float cn = fmaf(f_, cv[j], i_ * g_);
                cv[j] = cn;
                hv[j] = o_ * tanhfast(cn);
            }
            *(float2*)&cbuf[row0 * CB_STRIDE + u0]       = make_float2(cv[0], cv[1]);
            *(float2*)&cbuf[(row0 + 8) * CB_STRIDE + u0] = make_float2(cv[2], cv[3]);
            __half2 h01 = __floats2half2_rn(hv[0], hv[1]);
            __half2 h23 = __floats2half2_rn(hv[2], hv[3]);
            *(__half2*)(houtg + (size_t)row0 * 256 + u0)       = h01;
            *(__half2*)(houtg + (size_t)(row0 + 8) * 256 + u0) = h23;
            *(__half2*)(houts + row0 * SA_STRIDE + u0)         = h01;
            *(__half2*)(houts + (row0 + 8) * SA_STRIDE + u0)   = h23;
        }

        __syncthreads();
        if (tid == 0) st_rel(&g_prog[l * GPL + gg], (unsigned)(t + 1));
    }
}

// ------------------------------ output head ---------------------------------

__global__ void out_proj(const float* __restrict__ Wout,
                         const float* __restrict__ bout,
                         float* __restrict__ out) {
    int p = blockIdx.x * 8 + (threadIdx.x >> 5);   // (t*64+b), 16384 total
    int lane = threadIdx.x & 31;
    int t = p >> 6, b = p & 63;
    const __half* h = g_h16 + (size_t)(LAYERS - 1) * HLAYER +
                      (size_t)(t + 1) * HSLOT + (size_t)b * 256 + lane * 8;
    uint4 hv = *(const uint4*)h;
    const __half2* hh = (const __half2*)&hv;
    const float* w0 = Wout + lane * 8;
    const float* w1 = Wout + 256 + lane * 8;
    float s0 = 0.f, s1 = 0.f;
    #pragma unroll
    for (int j = 0; j < 4; ++j) {
        float2 f = __half22float2(hh[j]);
        s0 += f.x * w0[2 * j] + f.y * w0[2 * j + 1];
        s1 += f.x * w1[2 * j] + f.y * w1[2 * j + 1];
    }
    #pragma unroll
    for (int off = 16; off > 0; off >>= 1) {
        s0 += __shfl_xor_sync(0xffffffffu, s0, off);
        s1 += __shfl_xor_sync(0xffffffffu, s1, off);
    }
    if (lane == 0) {
        float e0 = __expf(-(s0 + bout[0]));
        float e1 = __expf(-(s1 + bout[1]));
        out[(size_t)b * (TSTEPS * 2) + t * 2 + 0] = __fdividef(1.f, 1.f + e0);
        out[(size_t)b * (TSTEPS * 2) + t * 2 + 1] = __fdividef(1.f, 1.f + e1);
    }
}

// ------------------------------- launcher -----------------------------------

extern "C" void kernel_launch(void* const* d_in, const int* in_sizes, int n_in,
                              void* d_out, int out_size) {
    const float* x    = (const float*)d_in[0];
    const float* Wih  = (const float*)d_in[1];
    const float* Whh  = (const float*)d_in[2];
    const float* bih  = (const float*)d_in[3];
    const float* bhh  = (const float*)d_in[4];
    const float* Wout = (const float*)d_in[5];
    const float* bout = (const float*)d_in[6];
    float* out = (float*)d_out;

    cudaFuncSetAttribute(lstm_persistent,
                         cudaFuncAttributeMaxDynamicSharedMemorySize, SMEM_BYTES);

    prep_wfrag16<<<102400, 256>>>(Wih, Whh);    // 26.2M packed fp16 fragments
    prep_bias_init<<<200, 256>>>(bih, bhh);     // bias permute + progress reset
    zero_h0<<<LAYERS, 256>>>();                 // h_{-1} = 0 slots (fp16)
    lstm_persistent<<<NCTA, 512, SMEM_BYTES>>>(x);
    out_proj<<<2048, 256>>>(Wout, bout, out);   // final sigmoid head
}

// round 15
// speedup vs baseline: 1.3387x; 1.1168x over previous
#include <cuda_runtime.h>
#include <cuda_fp16.h>
#include <cstdint>
#include <cstddef>

// ---------------------------------------------------------------------------
// 50-layer LSTM, persistent wavefront, fp16 m16n8k16 mma.sync.
//   B=64, T=256, D=H=256, L=50, O=2
//   R15: BATCH-split (CTA owns 32 batch rows x ALL 256 units):
//     - no peer handshake (two independent wavefront chains)
//     - h recurrence stays in SMEM (no h staging, no own-h round trip)
//     - GEMM 32x1024x512 per CTA; B via cp.async depth-4 pipeline
//   100 CTAs (1/SM), 512 threads, warp tile 32x64 gate-blocked.
// ---------------------------------------------------------------------------

#define LAYERS 50
#define TSTEPS 256
#define NCTA   (LAYERS*2)                  // 100 CTAs, 1 per SM
#define HSLOT  16384                       // 64*256 halves per time slot
#define HLAYER ((size_t)(TSTEPS+1)*HSLOT)

#define SA_STRIDE 520                      // halves per SMEM A row (32 rows)
#define CB_STRIDE 264                      // floats per cbuf row (256 units)
#define W_WARP_HALVES 32768                // per (l,wn): 32kt*4j*32lane*8h
#define NSTAGE 4
#define SB_STAGE 32768                     // bytes per B stage (16 warps * 2KB)
#define OFF_CB   (32*SA_STRIDE*2)                       // 33280
#define OFF_BIAS (OFF_CB + 32*CB_STRIDE*4)              // 67072
#define OFF_SB   (OFF_BIAS + 1024*4)                    // 71168
#define SMEM_BYTES (OFF_SB + NSTAGE*SB_STAGE)           // 202240

__device__ __half   g_h16[(size_t)LAYERS*HLAYER];                 // ~421 MB
__device__ __half   g_w16[(size_t)LAYERS*16*W_WARP_HALVES];       // ~52 MB
__device__ float    g_bias[LAYERS*1024];
__device__ unsigned g_prog[128];

// ------------------------------- helpers -----------------------------------

__device__ __forceinline__ unsigned ld_acq(const unsigned* p) {
    unsigned v;
    asm volatile("ld.acquire.gpu.u32 %0, [%1];" : "=r"(v) : "l"(p) : "memory");
    return v;
}
__device__ __forceinline__ void st_rel(unsigned* p, unsigned v) {
    asm volatile("st.release.gpu.u32 [%0], %1;" :: "l"(p), "r"(v) : "memory");
}
__device__ __forceinline__ void mma16(float* acc, const uint32_t a[4],
                                      uint32_t b0, uint32_t b1) {
    asm("mma.sync.aligned.m16n8k16.row.col.f32.f16.f16.f32 "
        "{%0,%1,%2,%3},{%4,%5,%6,%7},{%8,%9},{%0,%1,%2,%3};"
        : "+f"(acc[0]), "+f"(acc[1]), "+f"(acc[2]), "+f"(acc[3])
        : "r"(a[0]), "r"(a[1]), "r"(a[2]), "r"(a[3]), "r"(b0), "r"(b1));
}
__device__ __forceinline__ void ldsm4(uint32_t r[4], uint32_t saddr) {
    asm volatile("ldmatrix.sync.aligned.m8n8.x4.shared.b16 {%0,%1,%2,%3}, [%4];"
        : "=r"(r[0]), "=r"(r[1]), "=r"(r[2]), "=r"(r[3]) : "r"(saddr));
}
__device__ __forceinline__ void cpa16(uint32_t dst, const void* src) {
    asm volatile("cp.async.cg.shared.global [%0], [%1], 16;"
                 :: "r"(dst), "l"(src));
}
__device__ __forceinline__ void cpa_commit() {
    asm volatile("cp.async.commit_group;" ::: "memory");
}
__device__ __forceinline__ uint4 lds128(uint32_t addr) {
    uint4 v;
    asm volatile("ld.shared.v4.u32 {%0,%1,%2,%3}, [%4];"
        : "=r"(v.x), "=r"(v.y), "=r"(v.z), "=r"(v.w) : "r"(addr));
    return v;
}
__device__ __forceinline__ float tanhfast(float x) {
    float y;
    asm("tanh.approx.f32 %0, %1;" : "=f"(y) : "f"(x));
    return y;
}
__device__ __forceinline__ float sigm(float x) {          // 1 MUFU
    return fmaf(tanhfast(0.5f * x), 0.5f, 0.5f);
}

// ------------------------------ prep kernels --------------------------------

// Pack weights into uint4-loadable fp16 B fragments, gate-blocked columns.
// half index: [l][wn(16)][kt(32)][j(4)][lane(32)][h(8)]   (no batch split in W)
// Warp wn owns units [16wn,16wn+16); its 64 cols: nt = gate*2+up, col 0..7:
//   r = gate*256 + wn*16 + up*8 + col
__global__ void prep_wfrag16(const float* __restrict__ Wih,
                             const float* __restrict__ Whh) {
    size_t idx = (size_t)blockIdx.x * 256 + threadIdx.x;
    int h    = (int)(idx & 7);
    int lane = (int)((idx >> 3)  & 31);
    int j    = (int)((idx >> 8)  & 3);
    int kt   = (int)((idx >> 10) & 31);
    int wn   = (int)((idx >> 15) & 15);
    int l    = (int)(idx >> 19);
    if (l >= LAYERS) return;
    int jj = h >> 1, hb = h & 1;
    int nt  = j * 2 + (jj >> 1);
    int col = lane >> 2;
    int k   = kt * 16 + (lane & 3) * 2 + hb + (jj & 1) * 8;
    int gate = nt >> 1, up = nt & 1;
    int r = gate * 256 + wn * 16 + up * 8 + col;
    float v = (k < 256) ? Wih[((size_t)l * 1024 + r) * 256 + k]
                        : Whh[((size_t)l * 1024 + r) * 256 + (k - 256)];
    g_w16[idx] = __float2half(v);
}

// sbias[l][wn*64 + nt*8 + cc]
__global__ void prep_bias_init(const float* __restrict__ bih,
                               const float* __restrict__ bhh) {
    int idx = blockIdx.x * 256 + threadIdx.x;
    if (idx < LAYERS * 1024) {
        int l  = idx >> 10;
        int nn = idx & 1023;
        int wn = nn >> 6;
        int nt = (nn >> 3) & 7;
        int cc = nn & 7;
        int gate = nt >> 1, up = nt & 1;
        int r = gate * 256 + wn * 16 + up * 8 + cc;
        g_bias[idx] = bih[l * 1024 + r] + bhh[l * 1024 + r];
    }
    if (idx < 128) g_prog[idx] = 0;
}

__global__ void zero_h0() {
    uint4* p = (uint4*)(g_h16 + (size_t)blockIdx.x * HLAYER);  // slot 0
    for (int i = threadIdx.x; i < 2048; i += 256)
        p[i] = make_uint4(0u, 0u, 0u, 0u);
}

// --------------------------- persistent LSTM --------------------------------

__global__ void __launch_bounds__(512, 1)
lstm_persistent(const float* __restrict__ x) {
    extern __shared__ char smem[];
    __half* sA    = (__half*)smem;                       // 32 x 520 ([x|h])
    float*  cbuf  = (float*)(smem + OFF_CB);             // 32 x 264
    float*  sbias = (float*)(smem + OFF_BIAS);           // 1024

    const int l    = blockIdx.x >> 1;
    const int gg   = blockIdx.x & 1;       // batch half: rows [32gg, 32gg+32)
    const int tid  = threadIdx.x;
    const int lane = tid & 31;
    const int wn   = tid >> 5;             // 0..15 : unit group [16wn,16wn+16)
    const int q    = lane & 3;

    for (int i = tid; i < 1024; i += 512)
        sbias[i] = g_bias[l * 1024 + i];
    for (int i = tid; i < 32 * CB_STRIDE; i += 512) cbuf[i] = 0.f;
    for (int i = tid; i < 512; i += 512) {   // h_{-1} = 0 in sA h-region
        int row = i >> 4, c8 = i & 15;
        *(uint4*)(sA + row * SA_STRIDE + 256 + c8 * 8) =
            make_uint4(0u, 0u, 0u, 0u);
    }
    __syncthreads();

    const uint4* wv = (const uint4*)(g_w16 +
        (size_t)(l * 16 + wn) * W_WARP_HALVES);
    __half* hlayer = g_h16 + (size_t)l * HLAYER;
    const __half* hprev = (l > 0) ? (g_h16 + (size_t)(l - 1) * HLAYER) : nullptr;

    uint32_t smem_u32 = (uint32_t)__cvta_generic_to_shared(smem);
    uint32_t sA_base  = smem_u32;
    uint32_t sBw = smem_u32 + OFF_SB + wn * 2048 + lane * 16;

    const int rowA = lane & 15;
    const int kofA = (lane >> 4) * 8;

    float acc[2][8][4];        // [mt][nt][frag] : 64 regs

    for (int t = 0; t < TSTEPS; ++t) {
        // ---- wait: prev layer same batch-half >= t+1 (x ready) ----
        if (tid == 0 && l > 0) {
            while (ld_acq(&g_prog[(l - 1) * 2 + gg]) < (unsigned)(t + 1))
                __nanosleep(32);
        }
        __syncthreads();

        // ---- stage x_t -> sA[0,256)  (h region persists in SMEM) ----
        if (l == 0) {
            #pragma unroll
            for (int i = tid; i < 2048; i += 512) {       // 32 rows * 64 float4
                int row = i >> 6, c4 = i & 63;
                float4 v = __ldg((const float4*)(x +
                    ((size_t)(gg * 32 + row) * TSTEPS + t) * 256) + c4);
                __half2* dst = (__half2*)(sA + row * SA_STRIDE + c4 * 4);
                dst[0] = __floats2half2_rn(v.x, v.y);
                dst[1] = __floats2half2_rn(v.z, v.w);
            }
        } else {
            const __half* src = hprev + (size_t)(t + 1) * HSLOT +
                                (size_t)(gg * 32) * 256;
            #pragma unroll
            for (int i = tid; i < 1024; i += 512) {       // 32 rows * 16 uint4
                int row = i >> 5, c8 = i & 31;
                *(uint4*)(sA + row * SA_STRIDE + c8 * 8) =
                    __ldg((const uint4*)(src + (size_t)row * 256) + c8);
            }
        }

        // ---- init accumulators with bias ----
        #pragma unroll
        for (int nt = 0; nt < 8; ++nt) {
            float b0 = sbias[wn * 64 + nt * 8 + q * 2];
            float b1 = sbias[wn * 64 + nt * 8 + q * 2 + 1];
            acc[0][nt][0] = b0; acc[0][nt][1] = b1;
            acc[0][nt][2] = b0; acc[0][nt][3] = b1;
            acc[1][nt][0] = b0; acc[1][nt][1] = b1;
            acc[1][nt][2] = b0; acc[1][nt][3] = b1;
        }
        __syncthreads();

        // ---- GEMM: gates += [x_t | h_{t-1}] @ Wc^T  (32x1024x512) ----
        // B streamed via per-warp cp.async depth-4 pipeline; each lane
        // copies exactly the 4x16B it later lds128s -> no barriers needed.
        {
            #pragma unroll
            for (int s = 0; s < NSTAGE - 1; ++s) {        // prologue kt=0..2
                #pragma unroll
                for (int j = 0; j < 4; ++j)
                    cpa16(sBw + s * SB_STAGE + j * 512,
                          wv + s * 128 + j * 32 + lane);
                cpa_commit();
            }
            #pragma unroll 4
            for (int kt = 0; kt < 32; ++kt) {
                const int s = kt & (NSTAGE - 1);
                asm volatile("cp.async.wait_group %0;" :: "n"(NSTAGE - 2) : "memory");
                uint4 bb[4];
                #pragma unroll
                for (int j = 0; j < 4; ++j)
                    bb[j] = lds128(sBw + s * SB_STAGE + j * 512);
                uint32_t av[2][4];
                #pragma unroll
                for (int mt = 0; mt < 2; ++mt) {
                    uint32_t addr = sA_base + (uint32_t)(
                        ((mt * 16 + rowA) * SA_STRIDE + kt * 16 + kofA) * 2);
                    ldsm4(av[mt], addr);
                }
                if (kt < 32 - (NSTAGE - 1)) {
                    const int s2 = (kt + NSTAGE - 1) & (NSTAGE - 1);
                    #pragma unroll
                    for (int j = 0; j < 4; ++j)
                        cpa16(sBw + s2 * SB_STAGE + j * 512,
                              wv + (kt + NSTAGE - 1) * 128 + j * 32 + lane);
                }
                cpa_commit();
                #pragma unroll
                for (int j = 0; j < 4; ++j) {
                    mma16(acc[0][2 * j],     av[0], bb[j].x, bb[j].y);
                    mma16(acc[0][2 * j + 1], av[0], bb[j].z, bb[j].w);
                    mma16(acc[1][2 * j],     av[1], bb[j].x, bb[j].y);
                    mma16(acc[1][2 * j + 1], av[1], bb[j].z, bb[j].w);
                }
            }
        }
        __syncthreads();   // all LDSM done before sA h-region is rewritten

        // ---- elementwise LSTM update (tanh.approx, c in SMEM) ----
        // element (mt,up,j): row = mt*16 + (lane>>2) + (j>>1)*8,
        // unit u = wn*16 + up*8 + 2q + (j&1); gates nt = {up,2+up,4+up,6+up}
        __half* houtg = hlayer + (size_t)(t + 1) * HSLOT +
                        (size_t)(gg * 32) * 256;
        __half* houts = sA + 256;
        const int rbase = lane >> 2;
        const int ulb = wn * 16 + 2 * q;
        #pragma unroll
        for (int mt = 0; mt < 2; ++mt) {
            #pragma unroll
            for (int up = 0; up < 2; ++up) {
                int u    = ulb + up * 8;
                int row0 = mt * 16 + rbase;
                float2 c01 = *(float2*)&cbuf[row0 * CB_STRIDE + u];
                float2 c23 = *(float2*)&cbuf[(row0 + 8) * CB_STRIDE + u];
                float cv[4] = {c01.x, c01.y, c23.x, c23.y};
                float hv[4];
                #pragma unroll
                for (int j = 0; j < 4; ++j) {
                    float i_ = sigm(acc[mt][up][j]);
                    float f_ = sigm(acc[mt][2 + up][j]);
                    float g_ = tanhfast(acc[mt][4 + up][j]);
                    float o_ = sigm(acc[mt][6 + up][j]);
                    float cn = fmaf(f_, cv[j], i_ * g_);
                    cv[j] = cn;
                    hv[j] = o_ * tanhfast(cn);
                }
                *(float2*)&cbuf[row0 * CB_STRIDE + u]       = make_float2(cv[0], cv[1]);
                *(float2*)&cbuf[(row0 + 8) * CB_STRIDE + u] = make_float2(cv[2], cv[3]);
                __half2 h01 = __floats2half2_rn(hv[0], hv[1]);
                __half2 h23 = __floats2half2_rn(hv[2], hv[3]);
                *(__half2*)(houts + row0 * SA_STRIDE + u)         = h01;
                *(__half2*)(houts + (row0 + 8) * SA_STRIDE + u)   = h23;
                *(__half2*)(houtg + (size_t)row0 * 256 + u)       = h01;
                *(__half2*)(houtg + (size_t)(row0 + 8) * 256 + u) = h23;
            }
        }

        __syncthreads();
        if (tid == 0) st_rel(&g_prog[l * 2 + gg], (unsigned)(t + 1));
    }
}

// ------------------------------ output head ---------------------------------

__global__ void out_proj(const float* __restrict__ Wout,
                         const float* __restrict__ bout,
                         float* __restrict__ out) {
    int p = blockIdx.x * 8 + (threadIdx.x >> 5);   // (t*64+b), 16384 total
    int lane = threadIdx.x & 31;
    int t = p >> 6, b = p & 63;
    const __half* h = g_h16 + (size_t)(LAYERS - 1) * HLAYER +
                      (size_t)(t + 1) * HSLOT + (size_t)b * 256 + lane * 8;
    uint4 hv = *(const uint4*)h;
    const __half2* hh = (const __half2*)&hv;
    const float* w0 = Wout + lane * 8;
    const float* w1 = Wout + 256 + lane * 8;
    float s0 = 0.f, s1 = 0.f;
    #pragma unroll
    for (int j = 0; j < 4; ++j) {
        float2 f = __half22float2(hh[j]);
        s0 += f.x * w0[2 * j] + f.y * w0[2 * j + 1];
        s1 += f.x * w1[2 * j] + f.y * w1[2 * j + 1];
    }
    #pragma unroll
    for (int off = 16; off > 0; off >>= 1) {
        s0 += __shfl_xor_sync(0xffffffffu, s0, off);
        s1 += __shfl_xor_sync(0xffffffffu, s1, off);
    }
    if (lane == 0) {
        float e0 = __expf(-(s0 + bout[0]));
        float e1 = __expf(-(s1 + bout[1]));
        out[(size_t)b * (TSTEPS * 2) + t * 2 + 0] = __fdividef(1.f, 1.f + e0);
        out[(size_t)b * (TSTEPS * 2) + t * 2 + 1] = __fdividef(1.f, 1.f + e1);
    }
}

// ------------------------------- launcher -----------------------------------

extern "C" void kernel_launch(void* const* d_in, const int* in_sizes, int n_in,
                              void* d_out, int out_size) {
    const float* x    = (const float*)d_in[0];
    const float* Wih  = (const float*)d_in[1];
    const float* Whh  = (const float*)d_in[2];
    const float* bih  = (const float*)d_in[3];
    const float* bhh  = (const float*)d_in[4];
    const float* Wout = (const float*)d_in[5];
    const float* bout = (const float*)d_in[6];
    float* out = (float*)d_out;

    cudaFuncSetAttribute(lstm_persistent,
                         cudaFuncAttributeMaxDynamicSharedMemorySize, SMEM_BYTES);

    prep_wfrag16<<<102400, 256>>>(Wih, Whh);    // 26.2M packed fp16 fragments
    prep_bias_init<<<200, 256>>>(bih, bhh);     // bias permute + progress reset
    zero_h0<<<LAYERS, 256>>>();                 // h_{-1} = 0 slots (fp16)
    lstm_persistent<<<NCTA, 512, SMEM_BYTES>>>(x);
    out_proj<<<2048, 256>>>(Wout, bout, out);   // final sigmoid head
}

// round 17
// speedup vs baseline: 1.3886x; 1.0373x over previous
#include <cuda_runtime.h>
#include <cuda_fp16.h>
#include <cstdint>
#include <cstddef>

// ---------------------------------------------------------------------------
// 50-layer LSTM, persistent wavefront, fp16 m16n8k16 mma.sync.
//   B=64, T=256, D=H=256, L=50, O=2
//   R17: R16 with the x cp.async staging width FIXED (32 chunks/row, was 16).
//     - continuous depth-4 B ring (never restarts; kt 29..31 preload next
//       step's kt 0..2 during elementwise — weights are time-invariant)
//     - all-thread poll, bias-init overlaps x cp.async, 3 barriers/step
// ---------------------------------------------------------------------------

#define LAYERS 50
#define TSTEPS 256
#define NCTA   (LAYERS*2)                  // 100 CTAs, 1 per SM
#define HSLOT  16384                       // 64*256 halves per time slot
#define HLAYER ((size_t)(TSTEPS+1)*HSLOT)

#define SA_STRIDE 520                      // halves per SMEM A row (32 rows)
#define CB_STRIDE 264                      // floats per cbuf row (256 units)
#define W_WARP_HALVES 32768                // per (l,wn): 32kt*4j*32lane*8h
#define NSTAGE 4
#define SB_STAGE 32768                     // bytes per B stage (16 warps * 2KB)
#define OFF_CB   (32*SA_STRIDE*2)                       // 33280
#define OFF_BIAS (OFF_CB + 32*CB_STRIDE*4)              // 67072
#define OFF_SB   (OFF_BIAS + 1024*4)                    // 71168
#define SMEM_BYTES (OFF_SB + NSTAGE*SB_STAGE)           // 202240

__device__ __half   g_h16[(size_t)LAYERS*HLAYER];                 // ~421 MB
__device__ __half   g_w16[(size_t)LAYERS*16*W_WARP_HALVES];       // ~52 MB
__device__ float    g_bias[LAYERS*1024];
__device__ unsigned g_prog[128];

// ------------------------------- helpers -----------------------------------

__device__ __forceinline__ unsigned ld_acq(const unsigned* p) {
    unsigned v;
    asm volatile("ld.acquire.gpu.u32 %0, [%1];" : "=r"(v) : "l"(p) : "memory");
    return v;
}
__device__ __forceinline__ void st_rel(unsigned* p, unsigned v) {
    asm volatile("st.release.gpu.u32 [%0], %1;" :: "l"(p), "r"(v) : "memory");
}
__device__ __forceinline__ void mma16(float* acc, const uint32_t a[4],
                                      uint32_t b0, uint32_t b1) {
    asm("mma.sync.aligned.m16n8k16.row.col.f32.f16.f16.f32 "
        "{%0,%1,%2,%3},{%4,%5,%6,%7},{%8,%9},{%0,%1,%2,%3};"
        : "+f"(acc[0]), "+f"(acc[1]), "+f"(acc[2]), "+f"(acc[3])
        : "r"(a[0]), "r"(a[1]), "r"(a[2]), "r"(a[3]), "r"(b0), "r"(b1));
}
__device__ __forceinline__ void ldsm4(uint32_t r[4], uint32_t saddr) {
    asm volatile("ldmatrix.sync.aligned.m8n8.x4.shared.b16 {%0,%1,%2,%3}, [%4];"
        : "=r"(r[0]), "=r"(r[1]), "=r"(r[2]), "=r"(r[3]) : "r"(saddr));
}
__device__ __forceinline__ void cpa16(uint32_t dst, const void* src) {
    asm volatile("cp.async.cg.shared.global [%0], [%1], 16;"
                 :: "r"(dst), "l"(src));
}
__device__ __forceinline__ void cpa_commit() {
    asm volatile("cp.async.commit_group;" ::: "memory");
}
__device__ __forceinline__ uint4 lds128(uint32_t addr) {
    uint4 v;
    asm volatile("ld.shared.v4.u32 {%0,%1,%2,%3}, [%4];"
        : "=r"(v.x), "=r"(v.y), "=r"(v.z), "=r"(v.w) : "r"(addr));
    return v;
}
__device__ __forceinline__ float tanhfast(float x) {
    float y;
    asm("tanh.approx.f32 %0, %1;" : "=f"(y) : "f"(x));
    return y;
}
__device__ __forceinline__ float sigm(float x) {          // 1 MUFU
    return fmaf(tanhfast(0.5f * x), 0.5f, 0.5f);
}

// ------------------------------ prep kernels --------------------------------

// Pack weights into uint4-loadable fp16 B fragments, gate-blocked columns.
// half index: [l][wn(16)][kt(32)][j(4)][lane(32)][h(8)]
// Warp wn owns units [16wn,16wn+16); nt = gate*2+up; r = gate*256+wn*16+up*8+col
__global__ void prep_wfrag16(const float* __restrict__ Wih,
                             const float* __restrict__ Whh) {
    size_t idx = (size_t)blockIdx.x * 256 + threadIdx.x;
    int h    = (int)(idx & 7);
    int lane = (int)((idx >> 3)  & 31);
    int j    = (int)((idx >> 8)  & 3);
    int kt   = (int)((idx >> 10) & 31);
    int wn   = (int)((idx >> 15) & 15);
    int l    = (int)(idx >> 19);
    if (l >= LAYERS) return;
    int jj = h >> 1, hb = h & 1;
    int nt  = j * 2 + (jj >> 1);
    int col = lane >> 2;
    int k   = kt * 16 + (lane & 3) * 2 + hb + (jj & 1) * 8;
    int gate = nt >> 1, up = nt & 1;
    int r = gate * 256 + wn * 16 + up * 8 + col;
    float v = (k < 256) ? Wih[((size_t)l * 1024 + r) * 256 + k]
                        : Whh[((size_t)l * 1024 + r) * 256 + (k - 256)];
    g_w16[idx] = __float2half(v);
}

// sbias[l][wn*64 + nt*8 + cc]
__global__ void prep_bias_init(const float* __restrict__ bih,
                               const float* __restrict__ bhh) {
    int idx = blockIdx.x * 256 + threadIdx.x;
    if (idx < LAYERS * 1024) {
        int l  = idx >> 10;
        int nn = idx & 1023;
        int wn = nn >> 6;
        int nt = (nn >> 3) & 7;
        int cc = nn & 7;
        int gate = nt >> 1, up = nt & 1;
        int r = gate * 256 + wn * 16 + up * 8 + cc;
        g_bias[idx] = bih[l * 1024 + r] + bhh[l * 1024 + r];
    }
    if (idx < 128) g_prog[idx] = 0;
}

__global__ void zero_h0() {
    uint4* p = (uint4*)(g_h16 + (size_t)blockIdx.x * HLAYER);  // slot 0
    for (int i = threadIdx.x; i < 2048; i += 256)
        p[i] = make_uint4(0u, 0u, 0u, 0u);
}

// --------------------------- persistent LSTM --------------------------------

__global__ void __launch_bounds__(512, 1)
lstm_persistent(const float* __restrict__ x) {
    extern __shared__ char smem[];
    __half* sA    = (__half*)smem;                       // 32 x 520 ([x|h])
    float*  cbuf  = (float*)(smem + OFF_CB);             // 32 x 264
    float*  sbias = (float*)(smem + OFF_BIAS);           // 1024

    const int l    = blockIdx.x >> 1;
    const int gg   = blockIdx.x & 1;       // batch half: rows [32gg, 32gg+32)
    const int tid  = threadIdx.x;
    const int lane = tid & 31;
    const int wn   = tid >> 5;             // 0..15 : unit group [16wn,16wn+16)
    const int q    = lane & 3;

    for (int i = tid; i < 1024; i += 512)
        sbias[i] = g_bias[l * 1024 + i];
    for (int i = tid; i < 32 * CB_STRIDE; i += 512) cbuf[i] = 0.f;
    for (int i = tid; i < 512; i += 512) {   // h_{-1} = 0 in sA h-region
        int row = i >> 4, c8 = i & 15;
        *(uint4*)(sA + row * SA_STRIDE + 256 + c8 * 8) =
            make_uint4(0u, 0u, 0u, 0u);
    }
    __syncthreads();

    const uint4* wv = (const uint4*)(g_w16 +
        (size_t)(l * 16 + wn) * W_WARP_HALVES);
    __half* hlayer = g_h16 + (size_t)l * HLAYER;
    const __half* hprev = (l > 0) ? (g_h16 + (size_t)(l - 1) * HLAYER) : nullptr;

    uint32_t smem_u32 = (uint32_t)__cvta_generic_to_shared(smem);
    uint32_t sA_base  = smem_u32;
    uint32_t sBw = smem_u32 + OFF_SB + wn * 2048 + lane * 16;

    const int rowA = lane & 15;
    const int kofA = (lane >> 4) * 8;

    float acc[2][8][4];        // [mt][nt][frag] : 64 regs

    // ---- one-time B ring prologue (ring never restarts after this) ----
    #pragma unroll
    for (int s = 0; s < NSTAGE - 1; ++s) {
        #pragma unroll
        for (int j = 0; j < 4; ++j)
            cpa16(sBw + s * SB_STAGE + j * 512, wv + s * 128 + j * 32 + lane);
        cpa_commit();
    }

    for (int t = 0; t < TSTEPS; ++t) {
        // ---- wait: prev layer same batch-half >= t+1 (all threads poll) ----
        if (l > 0) {
            while (ld_acq(&g_prog[(l - 1) * 2 + gg]) < (unsigned)(t + 1))
                __nanosleep(32);
        }

        // ---- stage x_t -> sA[0,256)  (h region persists in SMEM) ----
        if (l == 0) {
            #pragma unroll
            for (int i = tid; i < 2048; i += 512) {       // 32 rows * 64 float4
                int row = i >> 6, c4 = i & 63;
                float4 v = __ldg((const float4*)(x +
                    ((size_t)(gg * 32 + row) * TSTEPS + t) * 256) + c4);
                __half2* dst = (__half2*)(sA + row * SA_STRIDE + c4 * 4);
                dst[0] = __floats2half2_rn(v.x, v.y);
                dst[1] = __floats2half2_rn(v.z, v.w);
            }
        } else {
            // full tile: 32 rows * 32 x 16B chunks = 16KB (2 chunks/thread)
            const __half* src = hprev + (size_t)(t + 1) * HSLOT +
                                (size_t)(gg * 32) * 256;
            int row = tid >> 4, c8 = tid & 15;
            cpa16(sA_base + (uint32_t)((row * SA_STRIDE + c8 * 8) * 2),
                  src + (size_t)row * 256 + c8 * 8);
            cpa16(sA_base + (uint32_t)((row * SA_STRIDE + (c8 + 16) * 8) * 2),
                  src + (size_t)row * 256 + (c8 + 16) * 8);
            cpa_commit();
        }

        // ---- init accumulators with bias (overlaps x cp.async) ----
        #pragma unroll
        for (int nt = 0; nt < 8; ++nt) {
            float b0 = sbias[wn * 64 + nt * 8 + q * 2];
            float b1 = sbias[wn * 64 + nt * 8 + q * 2 + 1];
            acc[0][nt][0] = b0; acc[0][nt][1] = b1;
            acc[0][nt][2] = b0; acc[0][nt][3] = b1;
            acc[1][nt][0] = b0; acc[1][nt][1] = b1;
            acc[1][nt][2] = b0; acc[1][nt][3] = b1;
        }
        // drain x (B lookahead groups landed during prior elementwise)
        asm volatile("cp.async.wait_group 0;" ::: "memory");
        __syncthreads();

        // ---- GEMM: gates += [x_t | h_{t-1}] @ Wc^T  (32x1024x512) ----
        // Continuous per-warp depth-4 B ring: at kt prefetch (kt+3) mod 32;
        // kt 29..31 thereby preload next step's kt 0..2 (weights invariant).
        {
            #pragma unroll 4
            for (int kt = 0; kt < 32; ++kt) {
                const int s = kt & (NSTAGE - 1);
                asm volatile("cp.async.wait_group %0;" :: "n"(NSTAGE - 2) : "memory");
                uint4 bb[4];
                #pragma unroll
                for (int j = 0; j < 4; ++j)
                    bb[j] = lds128(sBw + s * SB_STAGE + j * 512);
                uint32_t av[2][4];
                #pragma unroll
                for (int mt = 0; mt < 2; ++mt) {
                    uint32_t addr = sA_base + (uint32_t)(
                        ((mt * 16 + rowA) * SA_STRIDE + kt * 16 + kofA) * 2);
                    ldsm4(av[mt], addr);
                }
                {
                    const int ktn = (kt + NSTAGE - 1) & 31;
                    const int s2  = ktn & (NSTAGE - 1);
                    #pragma unroll
                    for (int j = 0; j < 4; ++j)
                        cpa16(sBw + s2 * SB_STAGE + j * 512,
                              wv + ktn * 128 + j * 32 + lane);
                }
                cpa_commit();
                #pragma unroll
                for (int j = 0; j < 4; ++j) {
                    mma16(acc[0][2 * j],     av[0], bb[j].x, bb[j].y);
                    mma16(acc[0][2 * j + 1], av[0], bb[j].z, bb[j].w);
                    mma16(acc[1][2 * j],     av[1], bb[j].x, bb[j].y);
                    mma16(acc[1][2 * j + 1], av[1], bb[j].z, bb[j].w);
                }
            }
        }
        __syncthreads();   // all LDSM done before sA h-region is rewritten

        // ---- elementwise LSTM update (tanh.approx, c in SMEM) ----
        // element (mt,up,j): row = mt*16 + (lane>>2) + (j>>1)*8,
        // unit u = wn*16 + up*8 + 2q + (j&1); gates nt = {up,2+up,4+up,6+up}
        __half* houtg = hlayer + (size_t)(t + 1) * HSLOT +
                        (size_t)(gg * 32) * 256;
        __half* houts = sA + 256;
        const int rbase = lane >> 2;
        const int ulb = wn * 16 + 2 * q;
        #pragma unroll
        for (int mt = 0; mt < 2; ++mt) {
            #pragma unroll
            for (int up = 0; up < 2; ++up) {
                int u    = ulb + up * 8;
                int row0 = mt * 16 + rbase;
                float2 c01 = *(float2*)&cbuf[row0 * CB_STRIDE + u];
                float2 c23 = *(float2*)&cbuf[(row0 + 8) * CB_STRIDE + u];
                float cv[4] = {c01.x, c01.y, c23.x, c23.y};
                float hv[4];
                #pragma unroll
                for (int j = 0; j < 4; ++j) {
                    float i_ = sigm(acc[mt][up][j]);
                    float f_ = sigm(acc[mt][2 + up][j]);
                    float g_ = tanhfast(acc[mt][4 + up][j]);
                    float o_ = sigm(acc[mt][6 + up][j]);
                    float cn = fmaf(f_, cv[j], i_ * g_);
                    cv[j] = cn;
                    hv[j] = o_ * tanhfast(cn);
                }
                *(float2*)&cbuf[row0 * CB_STRIDE + u]       = make_float2(cv[0], cv[1]);
                *(float2*)&cbuf[(row0 + 8) * CB_STRIDE + u] = make_float2(cv[2], cv[3]);
                __half2 h01 = __floats2half2_rn(hv[0], hv[1]);
                __half2 h23 = __floats2half2_rn(hv[2], hv[3]);
                *(__half2*)(houts + row0 * SA_STRIDE + u)         = h01;
                *(__half2*)(houts + (row0 + 8) * SA_STRIDE + u)   = h23;
                *(__half2*)(houtg + (size_t)row0 * 256 + u)       = h01;
                *(__half2*)(houtg + (size_t)(row0 + 8) * 256 + u) = h23;
            }
        }

        __syncthreads();
        if (tid == 0) st_rel(&g_prog[l * 2 + gg], (unsigned)(t + 1));
    }
}

// ------------------------------ output head ---------------------------------

__global__ void out_proj(const float* __restrict__ Wout,
                         const float* __restrict__ bout,
                         float* __restrict__ out) {
    int p = blockIdx.x * 8 + (threadIdx.x >> 5);   // (t*64+b), 16384 total
    int lane = threadIdx.x & 31;
    int t = p >> 6, b = p & 63;
    const __half* h = g_h16 + (size_t)(LAYERS - 1) * HLAYER +
                      (size_t)(t + 1) * HSLOT + (size_t)b * 256 + lane * 8;
    uint4 hv = *(const uint4*)h;
    const __half2* hh = (const __half2*)&hv;
    const float* w0 = Wout + lane * 8;
    const float* w1 = Wout + 256 + lane * 8;
    float s0 = 0.f, s1 = 0.f;
    #pragma unroll
    for (int j = 0; j < 4; ++j) {
        float2 f = __half22float2(hh[j]);
        s0 += f.x * w0[2 * j] + f.y * w0[2 * j + 1];
        s1 += f.x * w1[2 * j] + f.y * w1[2 * j + 1];
    }
    #pragma unroll
    for (int off = 16; off > 0; off >>= 1) {
        s0 += __shfl_xor_sync(0xffffffffu, s0, off);
        s1 += __shfl_xor_sync(0xffffffffu, s1, off);
    }
    if (lane == 0) {
        float e0 = __expf(-(s0 + bout[0]));
        float e1 = __expf(-(s1 + bout[1]));
        out[(size_t)b * (TSTEPS * 2) + t * 2 + 0] = __fdividef(1.f, 1.f + e0);
        out[(size_t)b * (TSTEPS * 2) + t * 2 + 1] = __fdividef(1.f, 1.f + e1);
    }
}

// ------------------------------- launcher -----------------------------------

extern "C" void kernel_launch(void* const* d_in, const int* in_sizes, int n_in,
                              void* d_out, int out_size) {
    const float* x    = (const float*)d_in[0];
    const float* Wih  = (const float*)d_in[1];
    const float* Whh  = (const float*)d_in[2];
    const float* bih  = (const float*)d_in[3];
    const float* bhh  = (const float*)d_in[4];
    const float* Wout = (const float*)d_in[5];
    const float* bout = (const float*)d_in[6];
    float* out = (float*)d_out;

    cudaFuncSetAttribute(lstm_persistent,
                         cudaFuncAttributeMaxDynamicSharedMemorySize, SMEM_BYTES);

    prep_wfrag16<<<102400, 256>>>(Wih, Whh);    // 26.2M packed fp16 fragments
    prep_bias_init<<<200, 256>>>(bih, bhh);     // bias permute + progress reset
    zero_h0<<<LAYERS, 256>>>();                 // h_{-1} = 0 slots (fp16)
    lstm_persistent<<<NCTA, 512, SMEM_BYTES>>>(x);
    out_proj<<<2048, 256>>>(Wout, bout, out);   // final sigmoid head
}